// round 5
// baseline (speedup 1.0000x reference)
#include <cuda_runtime.h>
#include <cuda_fp16.h>
#include <math.h>
#include <stdint.h>

// Problem constants
#define B   256
#define Hd  1024
#define L   400
#define V   50257
#define NTV 393              // ceil(V/128)

#define OUT_H    ((long)B * V)
#define OUT_AW   ((long)B * V + (long)B * Hd)

// ---------------- scratch (device globals) ---------------------------------
__device__ float g_scores[B * L];
__device__ float g_attn[B * Hd];
__device__ float g_o[B * Hd];
__device__ float g_logits[(long)B * V];
__device__ float g_part[4L * B * 3 * Hd];     // split-K partials (12.6 MB)
__device__ float g_rmax[(long)NTV * B];
__device__ float g_rsum[(long)NTV * B];
__device__ float g_lse[B];

// ---------------- helpers ---------------------------------------------------
__device__ __forceinline__ uint32_t smem_u32(const void* p) {
    uint32_t a;
    asm("{ .reg .u64 t; cvta.to.shared.u64 t, %1; cvt.u32.u64 %0, t; }" : "=r"(a) : "l"(p));
    return a;
}

__device__ __forceinline__ uint32_t h2bits(float x, float y) {
    __half2 h = __floats2half2_rn(x, y);
    return *(uint32_t*)&h;
}

#define SWZ64(x) ((x) ^ (((x) >> 3) & 0x30))

__device__ __forceinline__ void ldsm_x4(uint32_t* r, uint32_t addr) {
    asm volatile("ldmatrix.sync.aligned.m8n8.x4.shared.b16 {%0,%1,%2,%3}, [%4];"
                 : "=r"(r[0]), "=r"(r[1]), "=r"(r[2]), "=r"(r[3]) : "r"(addr));
}

__device__ __forceinline__ void mma_f16(float* c, const uint32_t* a, const uint32_t* b) {
    asm volatile(
        "mma.sync.aligned.m16n8k16.row.col.f32.f16.f16.f32 "
        "{%0,%1,%2,%3}, {%4,%5,%6,%7}, {%8,%9}, {%0,%1,%2,%3};"
        : "+f"(c[0]), "+f"(c[1]), "+f"(c[2]), "+f"(c[3])
        : "r"(a[0]), "r"(a[1]), "r"(a[2]), "r"(a[3]), "r"(b[0]), "r"(b[1]));
}

// fast exp (full-rate FFMA path)
__device__ __forceinline__ float fexp(float x)
{
    float t = fmaxf(x * 1.44269504f, -125.0f);
    float fi = t + 12582912.f;
    int   i = __float_as_int(fi);
    float fr = t - (fi - 12582912.f);
    float y = fr * 0.69314718f;
    float p = fmaf(y, 0.25f, 1.f);
    p = fmaf(y * p, 0.33333333f, 1.f);
    p = fmaf(y * p, 0.5f, 1.f);
    p = fmaf(y, p, 1.f);
    return __int_as_float((i + (127 - 0x4B400000)) << 23) * p;
}

// ---------------- fp16 tensor-core GEMM, M = 256 fixed ----------------------
// C[256,N] = concat_K(A1,A2) @ Bop (+bias)
// TRANSB=1: Bop = W[N,K]^T.  TRANSB=0: Bop = W[K,N] row-major.
// Split-K via blockIdx.z (chunkK), partial mode writes C + z*256*N.
// If rmax != null (direct logits mode): also emits per-tile row (max, expsum).
// 512 threads, 16 warps (4m x 4n), warp tile 64x32, BK=32, 2 stages x 24KB.
#define GH_SMEM 49152

template<int TRANSB>
__global__ __launch_bounds__(512, 1) void gemm_h16(
    const float* __restrict__ A1, const float* __restrict__ A2, int KA1,
    const float* __restrict__ W, const float* __restrict__ bias,
    float* __restrict__ C, float* __restrict__ rmax, float* __restrict__ rsum,
    int N, int K, int chunkK, int relu, int direct)
{
    extern __shared__ char smem[];
    const uint32_t sb = smem_u32(smem);

    const int t = threadIdx.x;
    const int lane = t & 31;
    const int wid = t >> 5;
    const int wm = wid >> 2;        // 0..3 (64-row slice)
    const int wn = wid & 3;         // 0..3 (32-col slice)
    const int g = lane >> 2;        // 0..7
    const int q = lane & 3;         // 0..3

    const int n0 = blockIdx.x * 128;
    const int kstart = blockIdx.z * chunkK;
    const int kend = min(kstart + chunkK, K);
    const int KA2 = K - KA1;

    float4 ra[4];       // A staging: 2048 cells / 512
    float4 rb[2];       // B staging

    float acc[4][4][4];
    #pragma unroll
    for (int i = 0; i < 4; i++)
        #pragma unroll
        for (int j = 0; j < 4; j++)
            #pragma unroll
            for (int v = 0; v < 4; v++) acc[i][j][v] = 0.f;

    auto loadA = [&](int k0) {
        #pragma unroll
        for (int i = 0; i < 4; i++) {
            int cell = t + i * 512;
            int row = cell >> 3;
            int c4 = (cell & 7) * 4;
            int k = k0 + c4;
            ra[i] = make_float4(0.f, 0.f, 0.f, 0.f);
            if (k < kend) {
                if (k < KA1) ra[i] = *(const float4*)&A1[(long)row * KA1 + k];
                else         ra[i] = *(const float4*)&A2[(long)row * KA2 + (k - KA1)];
            }
        }
    };
    auto loadB = [&](int k0) {
        if (TRANSB) {
            #pragma unroll
            for (int i = 0; i < 2; i++) {
                int cell = t + i * 512;
                int row = cell >> 3;
                int c4 = (cell & 7) * 4;
                int n = n0 + row, k = k0 + c4;
                rb[i] = make_float4(0.f, 0.f, 0.f, 0.f);
                if (n < N && k < kend) rb[i] = *(const float4*)&W[(long)n * K + k];
            }
        } else {
            #pragma unroll
            for (int i = 0; i < 2; i++) {
                int cell = t + i * 512;
                int kk = cell >> 5;
                int n4 = (cell & 31) * 4;
                int k = k0 + kk;
                rb[i] = make_float4(0.f, 0.f, 0.f, 0.f);
                if (k < kend && n0 + n4 < N) rb[i] = *(const float4*)&W[(long)k * N + n0 + n4];
            }
        }
    };
    auto storeAB = [&](int s) {
        char* Ab = smem + s * 24576;
        char* Bb = smem + s * 24576 + 16384;
        #pragma unroll
        for (int i = 0; i < 4; i++) {
            int cell = t + i * 512;
            int row = cell >> 3;
            int c4 = (cell & 7) * 4;
            uint32_t off = SWZ64((uint32_t)(row * 64 + c4 * 2));
            *(uint2*)(Ab + off) = make_uint2(h2bits(ra[i].x, ra[i].y), h2bits(ra[i].z, ra[i].w));
        }
        if (TRANSB) {
            #pragma unroll
            for (int i = 0; i < 2; i++) {
                int cell = t + i * 512;
                int row = cell >> 3;
                int c4 = (cell & 7) * 4;
                uint32_t off = SWZ64((uint32_t)(row * 64 + c4 * 2));
                *(uint2*)(Bb + off) = make_uint2(h2bits(rb[i].x, rb[i].y), h2bits(rb[i].z, rb[i].w));
            }
        } else {
            #pragma unroll
            for (int i = 0; i < 2; i++) {
                int cell = t + i * 512;
                int kk = cell >> 5;
                int n4 = (cell & 31) * 4;
                const float* f = (const float*)&rb[i];
                #pragma unroll
                for (int j = 0; j < 4; j++) {
                    uint32_t off = SWZ64((uint32_t)((n4 + j) * 64 + kk * 2));
                    *(__half*)(Bb + off) = __float2half_rn(f[j]);
                }
            }
        }
    };

    const int a_row = lane & 15;
    const int a_cb = (lane >> 4) << 4;
    const int b_row = (lane & 7) + ((lane >> 4) << 3);
    const int b_cb = ((lane >> 3) & 1) << 4;

    auto compute = [&](int s) {
        const uint32_t Ab = sb + s * 24576;
        const uint32_t Bb = Ab + 16384;
        #pragma unroll
        for (int ks = 0; ks < 2; ks++) {
            uint32_t af[4][4], bf[2][4];
            #pragma unroll
            for (int mt = 0; mt < 4; mt++) {
                int r = wm * 64 + mt * 16 + a_row;
                ldsm_x4(af[mt], Ab + SWZ64((uint32_t)(r * 64 + ks * 32 + a_cb)));
            }
            #pragma unroll
            for (int np = 0; np < 2; np++) {
                int r = wn * 32 + np * 16 + b_row;
                ldsm_x4(bf[np], Bb + SWZ64((uint32_t)(r * 64 + ks * 32 + b_cb)));
            }
            #pragma unroll
            for (int mt = 0; mt < 4; mt++)
                #pragma unroll
                for (int nt = 0; nt < 4; nt++)
                    mma_f16(acc[mt][nt], af[mt], &bf[nt >> 1][(nt & 1) * 2]);
        }
    };

    const int ntiles = (kend - kstart + 31) / 32;

    loadA(kstart); loadB(kstart);
    storeAB(0);
    __syncthreads();
    for (int c = 1; c < ntiles; c++) {
        loadA(kstart + c * 32); loadB(kstart + c * 32);
        compute((c - 1) & 1);
        __syncthreads();
        storeAB(c & 1);
        __syncthreads();
    }
    compute((ntiles - 1) & 1);

    // ---- epilogue: bias/relu into acc, write C ----
    float* Cw = direct ? C : (C + (long)blockIdx.z * 256 * N);
    #pragma unroll
    for (int mt = 0; mt < 4; mt++) {
        int row = wm * 64 + mt * 16 + g;
        #pragma unroll
        for (int nt = 0; nt < 4; nt++) {
            int col = n0 + wn * 32 + nt * 8 + 2 * q;
            if (direct) {
                float b0 = (col < N) ? bias[col] : 0.f;
                float b1 = (col + 1 < N) ? bias[col + 1] : 0.f;
                acc[mt][nt][0] += b0; acc[mt][nt][1] += b1;
                acc[mt][nt][2] += b0; acc[mt][nt][3] += b1;
                if (relu) {
                    #pragma unroll
                    for (int v = 0; v < 4; v++) acc[mt][nt][v] = fmaxf(acc[mt][nt][v], 0.f);
                }
            }
            if (col < N)     Cw[(long)row * N + col]           = acc[mt][nt][0];
            if (col + 1 < N) Cw[(long)row * N + col + 1]       = acc[mt][nt][1];
            if (col < N)     Cw[(long)(row + 8) * N + col]     = acc[mt][nt][2];
            if (col + 1 < N) Cw[(long)(row + 8) * N + col + 1] = acc[mt][nt][3];
        }
    }

    // ---- fused log-softmax partials (logits mode only; uniform branch) ----
    if (rmax != nullptr) {
        float* redm = (float*)smem;          // [4][256]
        float* reds = redm + 1024;
        __syncthreads();                     // smem stages now dead
        #pragma unroll
        for (int mt = 0; mt < 4; mt++) {
            #pragma unroll
            for (int half = 0; half < 2; half++) {
                float mv = -1e30f;
                float vals[8];
                #pragma unroll
                for (int nt = 0; nt < 4; nt++) {
                    #pragma unroll
                    for (int k2 = 0; k2 < 2; k2++) {
                        int col = n0 + wn * 32 + nt * 8 + 2 * q + k2;
                        float v = (col < N) ? acc[mt][nt][half * 2 + k2] : -1e30f;
                        vals[nt * 2 + k2] = v;
                        mv = fmaxf(mv, v);
                    }
                }
                float sv = 0.f;
                #pragma unroll
                for (int j = 0; j < 8; j++) sv += fexp(vals[j] - mv);
                #pragma unroll
                for (int off = 1; off <= 2; off <<= 1) {
                    float mo = __shfl_xor_sync(0xffffffff, mv, off);
                    float so = __shfl_xor_sync(0xffffffff, sv, off);
                    float mn = fmaxf(mv, mo);
                    sv = sv * fexp(mv - mn) + so * fexp(mo - mn);
                    mv = mn;
                }
                if (q == 0) {
                    int row = wm * 64 + mt * 16 + g + half * 8;
                    redm[wn * 256 + row] = mv;
                    reds[wn * 256 + row] = sv;
                }
            }
        }
        __syncthreads();
        if (t < 256) {
            float m = -1e30f, s = 0.f;
            #pragma unroll
            for (int w = 0; w < 4; w++) {
                float mw = redm[w * 256 + t], sw = reds[w * 256 + t];
                float mn = fmaxf(m, mw);
                s = s * fexp(m - mn) + sw * fexp(mw - mn);
                m = mn;
            }
            rmax[(long)blockIdx.x * 256 + t] = m;
            rsum[(long)blockIdx.x * 256 + t] = s;
        }
    }
}

// ---------------- split-K reduce (+bias, +relu) — deterministic -------------
__global__ void reduce_bias(const float* __restrict__ part, const float* __restrict__ bias,
                            float* __restrict__ out, int MN, int N, int SK, int relu)
{
    int idx = blockIdx.x * blockDim.x + threadIdx.x;
    if (idx >= MN) return;
    float s = 0.f;
    for (int c = 0; c < SK; c++) s += part[(long)c * MN + idx];
    if (bias) s += bias[idx % N];
    if (relu) s = fmaxf(s, 0.f);
    out[idx] = s;
}

// ---------------- fused GRU: split-K reduce of gi/gh + gates ----------------
__global__ void gru_fuse(const float* __restrict__ part, const float* __restrict__ hidden,
                         const float* __restrict__ bih, const float* __restrict__ bhh,
                         float* __restrict__ h_new)
{
    int idx = blockIdx.x * blockDim.x + threadIdx.x;
    if (idx >= B * Hd) return;
    int b = idx / Hd, j = idx - b * Hd;
    const long NN = 3 * Hd;
    const long MN = (long)B * NN;
    const float* giA = part;            // [2][B][3H]
    const float* ghA = part + 2 * MN;   // [2][B][3H]
    long base = (long)b * NN + j;

    float ir = giA[base] + giA[MN + base] + bih[j];
    float iz = giA[base + Hd] + giA[MN + base + Hd] + bih[j + Hd];
    float in_ = giA[base + 2 * Hd] + giA[MN + base + 2 * Hd] + bih[j + 2 * Hd];
    float hr = ghA[base] + ghA[MN + base] + bhh[j];
    float hz = ghA[base + Hd] + ghA[MN + base + Hd] + bhh[j + Hd];
    float hn = ghA[base + 2 * Hd] + ghA[MN + base + 2 * Hd] + bhh[j + 2 * Hd];

    float r = 1.f / (1.f + expf(-(ir + hr)));
    float z = 1.f / (1.f + expf(-(iz + hz)));
    float nn = tanhf(in_ + r * hn);
    h_new[idx] = (1.f - z) * nn + z * hidden[idx];
}

// ---------------- warp-per-row softmax (L=400) -------------------------------
__global__ void softmax_warp(const float* __restrict__ in, float* __restrict__ out, int n)
{
    int w = (blockIdx.x * blockDim.x + threadIdx.x) >> 5;
    int lid = threadIdx.x & 31;
    if (w >= B) return;
    const float* x = in + (long)w * n;
    float* y = out + (long)w * n;

    float m = -1e30f;
    for (int i = lid; i < n; i += 32) m = fmaxf(m, x[i]);
    #pragma unroll
    for (int o = 16; o > 0; o >>= 1) m = fmaxf(m, __shfl_xor_sync(0xffffffff, m, o));
    float s = 0.f;
    for (int i = lid; i < n; i += 32) s += fexp(x[i] - m);
    #pragma unroll
    for (int o = 16; o > 0; o >>= 1) s += __shfl_xor_sync(0xffffffff, s, o);
    float inv = 1.f / s;
    for (int i = lid; i < n; i += 32) y[i] = fexp(x[i] - m) * inv;
}

// ---------------- lse reduce over tiles --------------------------------------
__global__ void lse_reduce(const float* __restrict__ rmax, const float* __restrict__ rsum,
                           float* __restrict__ lse)
{
    int t = threadIdx.x;   // 256
    float m = -1e30f, s = 0.f;
    for (int tile = 0; tile < NTV; tile++) {
        float mw = rmax[(long)tile * 256 + t];
        float sw = rsum[(long)tile * 256 + t];
        float mn = fmaxf(m, mw);
        s = s * fexp(m - mn) + sw * fexp(mw - mn);
        m = mn;
    }
    lse[t] = m + logf(s);
}

// ---------------- final: logp = logits - lse ---------------------------------
__global__ void logp_final(const float* __restrict__ logits, const float* __restrict__ lse,
                           float* __restrict__ out)
{
    int col = blockIdx.x * 1024 + threadIdx.x;
    int row = blockIdx.y;
    if (col < V) {
        long i = (long)row * V + col;
        out[i] = logits[i] - lse[row];
    }
}

// ---------------- launch -----------------------------------------------------
extern "C" void kernel_launch(void* const* d_in, const int* in_sizes, int n_in,
                              void* d_out, int out_size)
{
    const float* embedded = (const float*)d_in[0];
    const float* hidden   = (const float*)d_in[1];
    const float* enc      = (const float*)d_in[2];
    const float* attn_W   = (const float*)d_in[3];
    const float* attn_b   = (const float*)d_in[4];
    const float* comb_W   = (const float*)d_in[5];
    const float* comb_b   = (const float*)d_in[6];
    const float* gru_Wih  = (const float*)d_in[7];
    const float* gru_Whh  = (const float*)d_in[8];
    const float* gru_bih  = (const float*)d_in[9];
    const float* gru_bhh  = (const float*)d_in[10];
    const float* out_W    = (const float*)d_in[11];
    const float* out_b    = (const float*)d_in[12];

    float* out = (float*)d_out;
    float* out_logp = out;
    float* out_h    = out + OUT_H;
    float* out_aw   = out + OUT_AW;

    float *scores, *attn, *o, *logits, *part, *rmax, *rsum, *lse;
    cudaGetSymbolAddress((void**)&scores, g_scores);
    cudaGetSymbolAddress((void**)&attn, g_attn);
    cudaGetSymbolAddress((void**)&o, g_o);
    cudaGetSymbolAddress((void**)&logits, g_logits);
    cudaGetSymbolAddress((void**)&part, g_part);
    cudaGetSymbolAddress((void**)&rmax, g_rmax);
    cudaGetSymbolAddress((void**)&rsum, g_rsum);
    cudaGetSymbolAddress((void**)&lse, g_lse);

    cudaFuncSetAttribute(gemm_h16<1>, cudaFuncAttributeMaxDynamicSharedMemorySize, GH_SMEM);
    cudaFuncSetAttribute(gemm_h16<0>, cudaFuncAttributeMaxDynamicSharedMemorySize, GH_SMEM);

    // 1. scores = [x|h] @ attn_W^T (+attn_b), split-K=8
    gemm_h16<1><<<dim3(4, 1, 8), 512, GH_SMEM>>>(embedded, hidden, Hd, attn_W, nullptr,
                                                 part, nullptr, nullptr,
                                                 L, 2 * Hd, 256, 0, 0);
    reduce_bias<<<(B * L + 255) / 256, 256>>>(part, attn_b, scores, B * L, L, 8, 0);

    // 2. attn_weights = softmax(scores) -> out_aw
    softmax_warp<<<32, 256>>>(scores, out_aw, L);

    // 3. attn_applied = attn_weights @ enc (NN), split-K=2
    gemm_h16<0><<<dim3(8, 1, 2), 512, GH_SMEM>>>(out_aw, nullptr, L, enc, nullptr,
                                                 part, nullptr, nullptr,
                                                 Hd, L, 224, 0, 0);
    reduce_bias<<<(B * Hd + 255) / 256, 256>>>(part, nullptr, attn, B * Hd, Hd, 2, 0);

    // 4. o = relu([x|attn] @ comb_W^T + comb_b), split-K=4
    gemm_h16<1><<<dim3(8, 1, 4), 512, GH_SMEM>>>(embedded, attn, Hd, comb_W, nullptr,
                                                 part, nullptr, nullptr,
                                                 Hd, 2 * Hd, 512, 0, 0);
    reduce_bias<<<(B * Hd + 255) / 256, 256>>>(part, comb_b, o, B * Hd, Hd, 4, 1);

    // 5. gi = o @ Wih^T ; gh = h @ Whh^T, split-K=2 each, fused gates
    gemm_h16<1><<<dim3(24, 1, 2), 512, GH_SMEM>>>(o, nullptr, Hd, gru_Wih, nullptr,
                                                  part, nullptr, nullptr,
                                                  3 * Hd, Hd, 512, 0, 0);
    gemm_h16<1><<<dim3(24, 1, 2), 512, GH_SMEM>>>(hidden, nullptr, Hd, gru_Whh, nullptr,
                                                  part + 2L * B * 3 * Hd, nullptr, nullptr,
                                                  3 * Hd, Hd, 512, 0, 0);
    gru_fuse<<<(B * Hd + 255) / 256, 256>>>(part, hidden, gru_bih, gru_bhh, out_h);

    // 6. logits = h_new @ out_W^T + out_b, W streamed ONCE, lse partials fused
    gemm_h16<1><<<dim3(NTV, 1, 1), 512, GH_SMEM>>>(out_h, nullptr, Hd, out_W, out_b,
                                                   logits, rmax, rsum,
                                                   V, Hd, Hd, 0, 1);

    // 7. lse + final subtract
    lse_reduce<<<1, 256>>>(rmax, rsum, lse);
    logp_final<<<dim3(50, B), 1024>>>(logits, lse, out_logp);
}